// round 4
// baseline (speedup 1.0000x reference)
#include <cuda_runtime.h>
#include <math.h>

typedef unsigned long long ull;

// ---------------- problem constants ----------------
#define BB    4
#define CC    64
#define HH    256
#define WW    256
#define NPIX  65536
#define NSQ   32768
#define NHEAD 4
#define DD    16

// ---------------- scratch ----------------
__device__ float g_tq[BB * CC * NPIX];
__device__ float g_tk[BB * CC * NPIX];
__device__ float g_tv[BB * CC * NPIX];
__device__ float g_qs[BB * CC * NSQ];
__device__ float g_ks[BB * CC * NSQ];
__device__ float g_vs[BB * CC * NSQ];
__device__ float g_ctx[BB * NHEAD * DD * DD];
__device__ float g_att[BB * CC * NPIX];
__device__ float g_m1[BB * 4 * CC * NPIX];
__device__ float g_m2[BB * 4 * CC * NPIX];
__device__ __align__(16) float g_w1T[128 * 256];
__device__ __align__(16) float g_w3T[256 * 128];
__device__ __align__(16) ull   g_rw2[64 * 128 * 30];   // conv5x5 [ic][oc][30] dup pairs
__device__ __align__(16) ull   g_wq2[64 * 64];         // qkv 1x1 weights [ic][oc] dup pairs
__device__ __align__(16) ull   g_wk2[64 * 64];
__device__ __align__(16) ull   g_wv2[64 * 64];

// ---------------- f32x2 helpers ----------------
__device__ __forceinline__ ull pk2(float lo, float hi) {
    ull r; asm("mov.b64 %0,{%1,%2};" : "=l"(r) : "f"(lo), "f"(hi)); return r;
}
__device__ __forceinline__ void upk2(float& lo, float& hi, ull v) {
    asm("mov.b64 {%0,%1},%2;" : "=f"(lo), "=f"(hi) : "l"(v));
}
__device__ __forceinline__ void fma2(ull& d, ull a, ull b) {
    asm("fma.rn.f32x2 %0,%1,%2,%0;" : "+l"(d) : "l"(a), "l"(b));
}
__device__ __forceinline__ float gelu_f(float x) {
    return 0.5f * x * (1.0f + erff(x * 0.7071067811865476f));
}

// ==================================================================
// K0: prepack
// ==================================================================
__global__ void __launch_bounds__(256) k_prep(
    const float* __restrict__ m1w, const float* __restrict__ m3w, const float* __restrict__ rw,
    const float* __restrict__ q1w, const float* __restrict__ k1w, const float* __restrict__ v1w)
{
    int i = blockIdx.x * 256 + threadIdx.x;
    if (i < 32768) {
        { int oc = i >> 7, ic = i & 127; g_w1T[ic * 256 + oc] = m1w[i]; }
        { int oc = i >> 8, ic = i & 255; g_w3T[ic * 128 + oc] = m3w[i]; }
    }
    if (i < 4096) {   // w[oc*64+ic]
        int oc = i >> 6, ic = i & 63;
        float v;
        v = q1w[i]; g_wq2[ic * 64 + oc] = pk2(v, v);
        v = k1w[i]; g_wk2[ic * 64 + oc] = pk2(v, v);
        v = v1w[i]; g_wv2[ic * 64 + oc] = pk2(v, v);
    }
    if (i < 204800) {
        int k = i % 25; int rest = i / 25;
        int ic = rest & 63, oc = rest >> 6;
        int ky = k / 5, kx = k - ky * 5;
        float v = rw[i];
        g_rw2[((long)ic * 128 + oc) * 30 + ky * 6 + kx] = pk2(v, v);
    }
}

// ==================================================================
// K1: fused 1x1 convs q/k/v, f32x2 pixel pairs.
// block 256: pp = t&31 (pixel pair), ch = t>>5 (8 oc each). 64 px per block.
// ==================================================================
__global__ void __launch_bounds__(256) k_qkv1x1(
    const float* __restrict__ x1, const float* __restrict__ x2,
    const float* __restrict__ bq, const float* __restrict__ bk, const float* __restrict__ bv)
{
    __shared__ __align__(16) ull s_x[64 * 32];   // [ic][pair] 16 KB
    __shared__ __align__(16) ull s_w[64 * 64];   // [ic][oc]   32 KB
    int t = threadIdx.x;
    int pp = t & 31, ch = t >> 5;
    long base = (long)blockIdx.x * 64;
    int b = (int)(base >> 16);
    int pix0 = (int)(base & 65535);
    int pixA = pix0 + 2 * pp;
    int parLo = ((pixA >> 8) + (pixA & 255)) & 1;   // parity of lo pixel; hi = 1-parLo

    // stage x1 pairs + q weights
    const float* xb1 = x1 + ((long)b * 64) * 65536 + pix0;
    for (int i = t; i < 2048; i += 256) {
        int ic = i >> 5, p = i & 31;
        float2 v = *(const float2*)(xb1 + (long)ic * 65536 + 2 * p);
        s_x[i] = pk2(v.x, v.y);
    }
    for (int i = t; i < 4096; i += 256) s_w[i] = g_wq2[i];
    __syncthreads();

    ull acc[8];
    // ---- Q ----
#pragma unroll
    for (int o = 0; o < 8; o++) acc[o] = 0;
#pragma unroll 8
    for (int ic = 0; ic < 64; ic++) {
        ull xv = s_x[ic * 32 + pp];
        const ulonglong2* wv = (const ulonglong2*)(s_w + ic * 64 + ch * 8);
#pragma unroll
        for (int j = 0; j < 4; j++) {
            ulonglong2 w2 = wv[j];
            fma2(acc[2 * j], w2.x, xv);
            fma2(acc[2 * j + 1], w2.y, xv);
        }
    }
#pragma unroll
    for (int o = 0; o < 8; o++) {
        int oc = ch * 8 + o;
        float bias = bq[oc];
        float lo, hi; upk2(lo, hi, acc[o]);
        lo = (parLo == 0) ? lo + bias : bias;     // q keeps nonanchor (par==0)
        hi = (parLo == 1) ? hi + bias : bias;
        *(float2*)(g_tq + ((long)b * 64 + oc) * 65536 + pixA) = make_float2(lo, hi);
    }
    __syncthreads();
    // ---- K (same x, anchor mask) ----
    for (int i = t; i < 4096; i += 256) s_w[i] = g_wk2[i];
    __syncthreads();
#pragma unroll
    for (int o = 0; o < 8; o++) acc[o] = 0;
#pragma unroll 8
    for (int ic = 0; ic < 64; ic++) {
        ull xv = s_x[ic * 32 + pp];
        const ulonglong2* wv = (const ulonglong2*)(s_w + ic * 64 + ch * 8);
#pragma unroll
        for (int j = 0; j < 4; j++) {
            ulonglong2 w2 = wv[j];
            fma2(acc[2 * j], w2.x, xv);
            fma2(acc[2 * j + 1], w2.y, xv);
        }
    }
#pragma unroll
    for (int o = 0; o < 8; o++) {
        int oc = ch * 8 + o;
        float bias = bk[oc];
        float lo, hi; upk2(lo, hi, acc[o]);
        lo = (parLo == 1) ? lo + bias : bias;     // k keeps anchor (par==1)
        hi = (parLo == 0) ? hi + bias : bias;
        *(float2*)(g_tk + ((long)b * 64 + oc) * 65536 + pixA) = make_float2(lo, hi);
    }
    __syncthreads();
    // ---- V (x2, no mask) ----
    const float* xb2 = x2 + ((long)b * 64) * 65536 + pix0;
    for (int i = t; i < 2048; i += 256) {
        int ic = i >> 5, p = i & 31;
        float2 v = *(const float2*)(xb2 + (long)ic * 65536 + 2 * p);
        s_x[i] = pk2(v.x, v.y);
    }
    for (int i = t; i < 4096; i += 256) s_w[i] = g_wv2[i];
    __syncthreads();
#pragma unroll
    for (int o = 0; o < 8; o++) acc[o] = 0;
#pragma unroll 8
    for (int ic = 0; ic < 64; ic++) {
        ull xv = s_x[ic * 32 + pp];
        const ulonglong2* wv = (const ulonglong2*)(s_w + ic * 64 + ch * 8);
#pragma unroll
        for (int j = 0; j < 4; j++) {
            ulonglong2 w2 = wv[j];
            fma2(acc[2 * j], w2.x, xv);
            fma2(acc[2 * j + 1], w2.y, xv);
        }
    }
#pragma unroll
    for (int o = 0; o < 8; o++) {
        int oc = ch * 8 + o;
        float bias = bv[oc];
        float lo, hi; upk2(lo, hi, acc[o]);
        *(float2*)(g_tv + ((long)b * 64 + oc) * 65536 + pixA) = make_float2(lo + bias, hi + bias);
    }
}

// ==================================================================
// K2: depthwise 3x3 + parity squeeze, 8 rows per block
// ==================================================================
__global__ void __launch_bounds__(128) k_dw_squeeze(
    const float* __restrict__ q2w, const float* __restrict__ q2b,
    const float* __restrict__ k2w, const float* __restrict__ k2b,
    const float* __restrict__ v2w, const float* __restrict__ v2b)
{
    int r0 = blockIdx.x * 8;
    int bc = blockIdx.y;
    int c = bc & 63;
    int which = blockIdx.z;
    const float* src; const float* wz; const float* bz; float* dst; int pbase;
    if (which == 0)      { src = g_tq; wz = q2w; bz = q2b; dst = g_qs; pbase = 0; }
    else if (which == 1) { src = g_tk; wz = k2w; bz = k2b; dst = g_ks; pbase = 1; }
    else                 { src = g_tv; wz = v2w; bz = v2b; dst = g_vs; pbase = 1; }

    __shared__ float srow[10][258];
    const float* base = src + (long)bc * 65536;
    for (int i = threadIdx.x; i < 10 * 258; i += 128) {
        int row = i / 258, xx = i % 258;
        int yy = r0 - 1 + row, x = xx - 1;
        srow[row][xx] = (yy >= 0 && yy < 256 && x >= 0 && x < 256) ? base[yy * 256 + x] : 0.f;
    }
    __syncthreads();
    float w[9];
#pragma unroll
    for (int i = 0; i < 9; i++) w[i] = wz[c * 9 + i];
    float bias = bz[c];
    int cp = threadIdx.x;
#pragma unroll
    for (int rr = 0; rr < 8; rr++) {
        int r = r0 + rr;
        int joff = pbase ? (1 - (r & 1)) : (r & 1);
        int j = 2 * cp + joff;
        float acc = bias;
#pragma unroll
        for (int ky = 0; ky < 3; ky++)
#pragma unroll
            for (int kx = 0; kx < 3; kx++)
                acc += srow[rr + ky][j + kx] * w[ky * 3 + kx];
        dst[(long)bc * 32768 + r * 128 + cp] = acc;
    }
}

// ==================================================================
// K3: k softmax
// ==================================================================
__global__ void __launch_bounds__(256) k_ksoftmax()
{
    int bc = blockIdx.x;
    float* row = g_ks + (long)bc * 32768;
    __shared__ float red[256];
    int t = threadIdx.x;
    float m = -1e30f;
    for (int i = t; i < 32768; i += 256) m = fmaxf(m, row[i]);
    red[t] = m; __syncthreads();
    for (int s = 128; s > 0; s >>= 1) { if (t < s) red[t] = fmaxf(red[t], red[t + s]); __syncthreads(); }
    m = red[0]; __syncthreads();
    float sum = 0.f;
    for (int i = t; i < 32768; i += 256) sum += __expf(row[i] - m);
    red[t] = sum; __syncthreads();
    for (int s = 128; s > 0; s >>= 1) { if (t < s) red[t] += red[t + s]; __syncthreads(); }
    float inv = 1.0f / red[0];
    for (int i = t; i < 32768; i += 256) row[i] = __expf(row[i] - m) * inv;
}

// ==================================================================
// K4: ctx
// ==================================================================
__global__ void __launch_bounds__(256) k_zero_ctx()
{
    int i = blockIdx.x * 256 + threadIdx.x;
    if (i < BB * NHEAD * DD * DD) g_ctx[i] = 0.f;
}
__global__ void __launch_bounds__(256) k_ctx()
{
    __shared__ float sk[16][257];
    __shared__ float sv[16][257];
    int bh = blockIdx.x;
    int ch = blockIdx.y;
    int b = bh >> 2, h = bh & 3;
    long rowbase = ((long)b * 64 + h * 16) * 32768 + ch * 256;
    int t = threadIdx.x;
    for (int i = t; i < 16 * 256; i += 256) {
        int d = i >> 8, n = i & 255;
        sk[d][n] = g_ks[rowbase + (long)d * 32768 + n];
        sv[d][n] = g_vs[rowbase + (long)d * 32768 + n];
    }
    __syncthreads();
    int d = t >> 4, e = t & 15;
    float a = 0.f;
#pragma unroll 8
    for (int n = 0; n < 256; n++) a += sk[d][n] * sv[e][n];
    atomicAdd(&g_ctx[(bh << 8) + (d << 4) + e], a);
}

// ==================================================================
// K5: q softmax + ctx^T q + unsqueeze
// ==================================================================
__global__ void __launch_bounds__(128) k_att()
{
    int r = blockIdx.x, b = blockIdx.y;
    __shared__ float cs[NHEAD * DD * DD];
    int t = threadIdx.x;
    for (int i = t; i < NHEAD * DD * DD; i += 128) cs[i] = g_ctx[b * (NHEAD * DD * DD) + i];
    __syncthreads();
    int cp = t;
    float qv[64];
    const float* qbase = g_qs + (long)b * 64 * 32768 + r * 128 + cp;
#pragma unroll
    for (int c = 0; c < 64; c++) qv[c] = qbase[(long)c * 32768];
    int odd = r & 1;
    float2* out = (float2*)(g_att + ((long)b * 64) * 65536 + (long)r * 256) + cp;
#pragma unroll
    for (int h = 0; h < 4; h++) {
        float m = -1e30f;
#pragma unroll
        for (int d = 0; d < 16; d++) m = fmaxf(m, qv[h * 16 + d]);
        float s = 0.f;
#pragma unroll
        for (int d = 0; d < 16; d++) { float e = __expf(qv[h * 16 + d] - m); qv[h * 16 + d] = e; s += e; }
        float inv = 1.0f / s;
#pragma unroll
        for (int e = 0; e < 16; e++) {
            float a = 0.f;
#pragma unroll
            for (int d = 0; d < 16; d++) a += cs[h * 256 + d * 16 + e] * qv[h * 16 + d];
            a *= inv;
            int c = h * 16 + e;
            float2 v = odd ? make_float2(0.f, a) : make_float2(a, 0.f);
            out[(long)c * 32768] = v;
        }
    }
}

// ==================================================================
// K6: conv5x5 (64->128), f32x2, 16 oc/block, tile 8x32, double-buffered.
// ==================================================================
#define C5_INW 36
#define C5_INE 35
#define C5_NIN (12*C5_INE)
#define C5_NW  480

__global__ void __launch_bounds__(256, 2) k_conv5x5(
    const float* __restrict__ rb, float* __restrict__ out)
{
    __shared__ __align__(16) ull s_in2[2][12 * C5_INW];
    __shared__ __align__(16) ull s_w2[2][C5_NW];
    int t = threadIdx.x;
    int bz = blockIdx.z;
    int b = bz >> 3, ocb = (bz & 7) * 16;
    int y0 = blockIdx.y * 8, x0 = blockIdx.x * 32;
    int os = t & 7, g = t >> 3;
    int py = g >> 2;
    int gxp = (g & 3) * 2;
    int o0 = ocb + 2 * os;

    int iyA = t / C5_INE, ixA = t - iyA * C5_INE;
    int gyA = y0 - 2 + iyA, gxA = x0 - 2 + ixA;
    bool yokA = (gyA >= 0 && gyA < 256);
    bool a0ok = yokA && (gxA >= 0) && (gxA < 256);
    bool a1ok = yokA && (gxA + 1 >= 0) && (gxA + 1 < 256);
    int offA = gyA * 256 + gxA;
    int iB = t + 256;
    bool hasB = iB < C5_NIN;
    int iyB = iB / C5_INE, ixB = iB - iyB * C5_INE;
    int gyB = y0 - 2 + iyB, gxB = x0 - 2 + ixB;
    bool yokB = (gyB >= 0 && gyB < 256);
    bool b0ok = hasB && yokB && (gxB >= 0) && (gxB < 256);
    bool b1ok = hasB && yokB && (gxB + 1 >= 0) && (gxB + 1 < 256);
    int offB = gyB * 256 + gxB;
    int sA = iyA * C5_INW + ixA;
    int sB = iyB * C5_INW + ixB;
    bool hasW2 = (t + 256) < C5_NW;
    long wbase = (long)ocb * 30 + t;

    const float* inb = g_att + (long)b * 64 * 65536;
    float bv0 = rb[o0], bv1 = rb[o0 + 1];
    ull acc0[4], acc1[4];
#pragma unroll
    for (int pp = 0; pp < 4; pp++) { acc0[pp] = pk2(bv0, bv0); acc1[pp] = pk2(bv1, bv1); }

    {
        const float* p = inb + offA;
        float va0 = a0ok ? p[0] : 0.f;
        float va1 = a1ok ? p[1] : 0.f;
        s_in2[0][sA] = pk2(va0, va1);
        if (hasB) {
            const float* q = inb + offB;
            float vb0 = b0ok ? q[0] : 0.f;
            float vb1 = b1ok ? q[1] : 0.f;
            s_in2[0][sB] = pk2(vb0, vb1);
        }
        s_w2[0][t] = g_rw2[wbase];
        if (hasW2) s_w2[0][t + 256] = g_rw2[wbase + 256];
    }
    __syncthreads();

    for (int ic = 0; ic < 64; ic++) {
        int cur = ic & 1;
        float va0 = 0.f, va1 = 0.f, vb0 = 0.f, vb1 = 0.f;
        ull w0v = 0, w1v = 0;
        if (ic < 63) {
            const float* p = inb + (long)(ic + 1) * 65536 + offA;
            va0 = a0ok ? p[0] : 0.f;
            va1 = a1ok ? p[1] : 0.f;
            if (hasB) {
                const float* q = inb + (long)(ic + 1) * 65536 + offB;
                vb0 = b0ok ? q[0] : 0.f;
                vb1 = b1ok ? q[1] : 0.f;
            }
            long wb = (long)(ic + 1) * (128 * 30) + wbase;
            w0v = g_rw2[wb];
            if (hasW2) w1v = g_rw2[wb + 256];
        }

        const ull* w0 = s_w2[cur] + (2 * os) * 30;
        const ull* w1 = w0 + 30;
#pragma unroll
        for (int ky = 0; ky < 5; ky++) {
            ulonglong2 waA = *(const ulonglong2*)(w0 + ky * 6);
            ulonglong2 waB = *(const ulonglong2*)(w0 + ky * 6 + 2);
            ull wa4 = w0[ky * 6 + 4];
            ulonglong2 wbA = *(const ulonglong2*)(w1 + ky * 6);
            ulonglong2 wbB = *(const ulonglong2*)(w1 + ky * 6 + 2);
            ull wb4 = w1[ky * 6 + 4];
            const ull* rowp = s_in2[cur] + (py + ky) * C5_INW;
#pragma unroll
            for (int pp = 0; pp < 4; pp++) {
                int xx = gxp + 8 * pp;
                ulonglong2 mA = *(const ulonglong2*)(rowp + xx);
                ulonglong2 mB = *(const ulonglong2*)(rowp + xx + 2);
                ull m4 = rowp[xx + 4];
                fma2(acc0[pp], waA.x, mA.x); fma2(acc1[pp], wbA.x, mA.x);
                fma2(acc0[pp], waA.y, mA.y); fma2(acc1[pp], wbA.y, mA.y);
                fma2(acc0[pp], waB.x, mB.x); fma2(acc1[pp], wbB.x, mB.x);
                fma2(acc0[pp], waB.y, mB.y); fma2(acc1[pp], wbB.y, mB.y);
                fma2(acc0[pp], wa4, m4);     fma2(acc1[pp], wb4, m4);
            }
        }

        if (ic < 63) {
            int nxt = cur ^ 1;
            s_in2[nxt][sA] = pk2(va0, va1);
            if (hasB) s_in2[nxt][sB] = pk2(vb0, vb1);
            s_w2[nxt][t] = w0v;
            if (hasW2) s_w2[nxt][t + 256] = w1v;
        }
        __syncthreads();
    }

    int gy = y0 + py;
    long base0 = ((long)b * 128 + o0) * 65536 + (long)gy * 256 + x0;
#pragma unroll
    for (int pp = 0; pp < 4; pp++) {
        int xx = gxp + 8 * pp;
        float lo, hi;
        upk2(lo, hi, acc0[pp]);
        *(float2*)(out + base0 + xx) = make_float2(lo, hi);
        upk2(lo, hi, acc1[pp]);
        *(float2*)(out + base0 + 65536 + xx) = make_float2(lo, hi);
    }
}

// ==================================================================
// K7: m1 = gelu(conv1x1 128->256), weight reg double-buffer
// ==================================================================
__global__ void __launch_bounds__(128) k_m1(
    const float* __restrict__ att, const float* __restrict__ bias)
{
    __shared__ __align__(16) float sbuf[8448];
    __shared__ __align__(16) float s_wT[2048];
    int t = threadIdx.x;
    long pix0 = (long)blockIdx.x * 32;
    int b = (int)(pix0 >> 16);
    int pp0 = (int)(pix0 & 65535);
    const float* ab = att + ((long)b * 128) * 65536 + pp0;
#pragma unroll 4
    for (int i = t; i < 4096; i += 128) {
        int ic = i >> 5, p = i & 31;
        sbuf[i] = ab[(long)ic * 65536 + p];
    }
    int oc0 = 2 * t;
    float b0 = bias[oc0], b1 = bias[oc0 + 1];
    ull acc0[16], acc1[16];
#pragma unroll
    for (int j = 0; j < 16; j++) { acc0[j] = pk2(b0, b0); acc1[j] = pk2(b1, b1); }

    float4 wreg[4];
#pragma unroll
    for (int j = 0; j < 4; j++) wreg[j] = *(const float4*)(g_w1T + (t + j * 128) * 4);

    for (int c8 = 0; c8 < 128; c8 += 8) {
        __syncthreads();
#pragma unroll
        for (int j = 0; j < 4; j++) *(float4*)(s_wT + (t + j * 128) * 4) = wreg[j];
        __syncthreads();
        if (c8 + 8 < 128) {
            const float* src = g_w1T + (c8 + 8) * 256;
#pragma unroll
            for (int j = 0; j < 4; j++) wreg[j] = *(const float4*)(src + (t + j * 128) * 4);
        }
#pragma unroll
        for (int k = 0; k < 8; k++) {
            ull wp = *(const ull*)(s_wT + k * 256 + oc0);
            float f0, f1; upk2(f0, f1, wp);
            ull w2a = pk2(f0, f0), w2b = pk2(f1, f1);
            const ulonglong2* xr = (const ulonglong2*)(sbuf + (c8 + k) * 32);
#pragma unroll
            for (int j = 0; j < 8; j++) {
                ulonglong2 x2 = xr[j];
                fma2(acc0[2 * j],     w2a, x2.x); fma2(acc0[2 * j + 1], w2a, x2.y);
                fma2(acc1[2 * j],     w2b, x2.x); fma2(acc1[2 * j + 1], w2b, x2.y);
            }
        }
    }
    __syncthreads();
#pragma unroll
    for (int j = 0; j < 16; j++) {
        float lo, hi;
        upk2(lo, hi, acc0[j]);
        sbuf[oc0 * 33 + 2 * j]     = gelu_f(lo);
        sbuf[oc0 * 33 + 2 * j + 1] = gelu_f(hi);
        upk2(lo, hi, acc1[j]);
        sbuf[(oc0 + 1) * 33 + 2 * j]     = gelu_f(lo);
        sbuf[(oc0 + 1) * 33 + 2 * j + 1] = gelu_f(hi);
    }
    __syncthreads();
    float* ob = g_m1 + ((long)b * 256) * 65536 + pp0;
#pragma unroll 4
    for (int i = t; i < 8192; i += 128) {
        int o = i >> 5, p = i & 31;
        ob[(long)o * 65536 + p] = sbuf[o * 33 + p];
    }
}

// ==================================================================
// K8: m2 = gelu(depthwise 3x3, 256 ch), 8 rows per block
// ==================================================================
__global__ void __launch_bounds__(256) k_m2(
    const float* __restrict__ w, const float* __restrict__ bias)
{
    int r0 = blockIdx.x * 8;
    int bc = blockIdx.y;
    int c = bc & 255;
    const float* base = g_m1 + (long)bc * 65536;
    __shared__ float srow[10][258];
    for (int i = threadIdx.x; i < 10 * 258; i += 256) {
        int row = i / 258, xx = i % 258;
        int yy = r0 - 1 + row, x = xx - 1;
        srow[row][xx] = (yy >= 0 && yy < 256 && x >= 0 && x < 256) ? base[yy * 256 + x] : 0.f;
    }
    __syncthreads();
    float wl[9];
#pragma unroll
    for (int i = 0; i < 9; i++) wl[i] = w[c * 9 + i];
    float bv = bias[c];
    int x = threadIdx.x;
#pragma unroll
    for (int rr = 0; rr < 8; rr++) {
        float acc = bv;
#pragma unroll
        for (int ky = 0; ky < 3; ky++)
#pragma unroll
            for (int kx = 0; kx < 3; kx++)
                acc += srow[rr + ky][x + kx] * wl[ky * 3 + kx];
        g_m2[(long)bc * 65536 + (long)(r0 + rr) * 256 + x] = gelu_f(acc);
    }
}

// ==================================================================
// K9: out += conv1x1(m2, 256->128), weight reg double-buffer
// ==================================================================
__global__ void __launch_bounds__(64) k_m3(
    float* __restrict__ out, const float* __restrict__ bias)
{
    __shared__ __align__(16) float sbuf[8448];
    __shared__ __align__(16) float s_wT[1024];
    int t = threadIdx.x;
    long pix0 = (long)blockIdx.x * 32;
    int b = (int)(pix0 >> 16);
    int pp0 = (int)(pix0 & 65535);
    const float* ib = g_m2 + ((long)b * 256) * 65536 + pp0;
#pragma unroll 8
    for (int i = t; i < 8192; i += 64) {
        int ic = i >> 5, p = i & 31;
        sbuf[i] = ib[(long)ic * 65536 + p];
    }
    int oc0 = 2 * t;
    float b0 = bias[oc0], b1 = bias[oc0 + 1];
    ull acc0[16], acc1[16];
#pragma unroll
    for (int j = 0; j < 16; j++) { acc0[j] = pk2(b0, b0); acc1[j] = pk2(b1, b1); }

    float4 wreg[4];
#pragma unroll
    for (int j = 0; j < 4; j++) wreg[j] = *(const float4*)(g_w3T + (t + j * 64) * 4);

    for (int c8 = 0; c8 < 256; c8 += 8) {
        __syncthreads();
#pragma unroll
        for (int j = 0; j < 4; j++) *(float4*)(s_wT + (t + j * 64) * 4) = wreg[j];
        __syncthreads();
        if (c8 + 8 < 256) {
            const float* src = g_w3T + (c8 + 8) * 128;
#pragma unroll
            for (int j = 0; j < 4; j++) wreg[j] = *(const float4*)(src + (t + j * 64) * 4);
        }
#pragma unroll
        for (int k = 0; k < 8; k++) {
            ull wp = *(const ull*)(s_wT + k * 128 + oc0);
            float f0, f1; upk2(f0, f1, wp);
            ull w2a = pk2(f0, f0), w2b = pk2(f1, f1);
            const ulonglong2* xr = (const ulonglong2*)(sbuf + (c8 + k) * 32);
#pragma unroll
            for (int j = 0; j < 8; j++) {
                ulonglong2 x2 = xr[j];
                fma2(acc0[2 * j],     w2a, x2.x); fma2(acc0[2 * j + 1], w2a, x2.y);
                fma2(acc1[2 * j],     w2b, x2.x); fma2(acc1[2 * j + 1], w2b, x2.y);
            }
        }
    }
    __syncthreads();
#pragma unroll
    for (int j = 0; j < 16; j++) {
        float lo, hi;
        upk2(lo, hi, acc0[j]);
        sbuf[oc0 * 33 + 2 * j]     = lo;
        sbuf[oc0 * 33 + 2 * j + 1] = hi;
        upk2(lo, hi, acc1[j]);
        sbuf[(oc0 + 1) * 33 + 2 * j]     = lo;
        sbuf[(oc0 + 1) * 33 + 2 * j + 1] = hi;
    }
    __syncthreads();
    float* ob = out + ((long)b * 128) * 65536 + pp0;
#pragma unroll 8
    for (int i = t; i < 4096; i += 64) {
        int o = i >> 5, p = i & 31;
        long a = (long)o * 65536 + p;
        ob[a] = ob[a] + sbuf[o * 33 + p];
    }
}

// ==================================================================
extern "C" void kernel_launch(void* const* d_in, const int* in_sizes, int n_in,
                              void* d_out, int out_size)
{
    const float* x1  = (const float*)d_in[0];
    const float* x2  = (const float*)d_in[1];
    const float* q1w = (const float*)d_in[2];  const float* q1b = (const float*)d_in[3];
    const float* q2w = (const float*)d_in[4];  const float* q2b = (const float*)d_in[5];
    const float* k1w = (const float*)d_in[6];  const float* k1b = (const float*)d_in[7];
    const float* k2w = (const float*)d_in[8];  const float* k2b = (const float*)d_in[9];
    const float* v1w = (const float*)d_in[10]; const float* v1b = (const float*)d_in[11];
    const float* v2w = (const float*)d_in[12]; const float* v2b = (const float*)d_in[13];
    const float* rw  = (const float*)d_in[14]; const float* rb  = (const float*)d_in[15];
    const float* m1w = (const float*)d_in[16]; const float* m1b = (const float*)d_in[17];
    const float* m2w = (const float*)d_in[18]; const float* m2b = (const float*)d_in[19];
    const float* m3w = (const float*)d_in[20]; const float* m3b = (const float*)d_in[21];
    float* out = (float*)d_out;

    // scratch target for the profiling probe (g_tq is dead after k_dw_squeeze)
    void* tq_addr = nullptr;
    cudaGetSymbolAddress(&tq_addr, g_tq);

    k_prep<<<800, 256>>>(m1w, m3w, rw, q1w, k1w, v1w);                  // idx 0
    k_qkv1x1<<<4096, 256>>>(x1, x2, q1b, k1b, v1b);                     // idx 1
    k_dw_squeeze<<<dim3(32, 256, 3), 128>>>(q2w, q2b, k2w, k2b, v2w, v2b); // idx 2
    // ---- profiling probe: quarter-grid conv5x5 clone, writes dead g_tq ----
    k_conv5x5<<<dim3(8, 32, 8), 256>>>(rb, (float*)tq_addr);            // idx 3 (ncu captures this)
    k_ksoftmax<<<256, 256>>>();                                          // idx 4
    k_zero_ctx<<<16, 256>>>();                                           // idx 5
    k_ctx<<<dim3(16, 128), 256>>>();                                     // idx 6
    k_att<<<dim3(256, 4), 128>>>();                                      // idx 7
    k_conv5x5<<<dim3(8, 32, 32), 256>>>(rb, out);                        // idx 8
    k_m1<<<8192, 128>>>(out, m1b);                                       // idx 9
    k_m2<<<dim3(32, 1024), 256>>>(m2w, m2b);                             // idx 10
    k_m3<<<8192, 64>>>(out, m3b);                                        // idx 11
}

// round 5
// speedup vs baseline: 1.4485x; 1.4485x over previous
#include <cuda_runtime.h>
#include <math.h>

typedef unsigned long long ull;

// ---------------- problem constants ----------------
#define BB    4
#define CC    64
#define HH    256
#define WW    256
#define NPIX  65536
#define NSQ   32768
#define NHEAD 4
#define DD    16

// ---------------- scratch ----------------
__device__ float g_tq[BB * CC * NPIX];
__device__ float g_tk[BB * CC * NPIX];
__device__ float g_tv[BB * CC * NPIX];
__device__ float g_qs[BB * CC * NSQ];
__device__ float g_ks[BB * CC * NSQ];
__device__ float g_vs[BB * CC * NSQ];
__device__ float g_ctx[BB * NHEAD * DD * DD];
__device__ float g_att[BB * CC * NPIX];
__device__ float g_m1[BB * 4 * CC * NPIX];
__device__ float g_m2[BB * 4 * CC * NPIX];
__device__ __align__(16) float g_w1T[128 * 256];
__device__ __align__(16) float g_w3T[256 * 128];
__device__ __align__(16) ull   g_rw2[64 * 128 * 30];   // conv5x5 [ic][oc][30] dup pairs
__device__ __align__(16) ull   g_wq2[64 * 64];
__device__ __align__(16) ull   g_wk2[64 * 64];
__device__ __align__(16) ull   g_wv2[64 * 64];

// ---------------- f32x2 helpers ----------------
__device__ __forceinline__ ull pk2(float lo, float hi) {
    ull r; asm("mov.b64 %0,{%1,%2};" : "=l"(r) : "f"(lo), "f"(hi)); return r;
}
__device__ __forceinline__ void upk2(float& lo, float& hi, ull v) {
    asm("mov.b64 {%0,%1},%2;" : "=f"(lo), "=f"(hi) : "l"(v));
}
__device__ __forceinline__ void fma2(ull& d, ull a, ull b) {
    asm("fma.rn.f32x2 %0,%1,%2,%0;" : "+l"(d) : "l"(a), "l"(b));
}
__device__ __forceinline__ float gelu_f(float x) {
    return 0.5f * x * (1.0f + erff(x * 0.7071067811865476f));
}

// ==================================================================
// K0: prepack
// ==================================================================
__global__ void __launch_bounds__(256) k_prep(
    const float* __restrict__ m1w, const float* __restrict__ m3w, const float* __restrict__ rw,
    const float* __restrict__ q1w, const float* __restrict__ k1w, const float* __restrict__ v1w)
{
    int i = blockIdx.x * 256 + threadIdx.x;
    if (i < 32768) {
        { int oc = i >> 7, ic = i & 127; g_w1T[ic * 256 + oc] = m1w[i]; }
        { int oc = i >> 8, ic = i & 255; g_w3T[ic * 128 + oc] = m3w[i]; }
    }
    if (i < 4096) {
        int oc = i >> 6, ic = i & 63;
        float v;
        v = q1w[i]; g_wq2[ic * 64 + oc] = pk2(v, v);
        v = k1w[i]; g_wk2[ic * 64 + oc] = pk2(v, v);
        v = v1w[i]; g_wv2[ic * 64 + oc] = pk2(v, v);
    }
    if (i < 204800) {
        int k = i % 25; int rest = i / 25;
        int ic = rest & 63, oc = rest >> 6;
        int ky = k / 5, kx = k - ky * 5;
        float v = rw[i];
        g_rw2[((long)ic * 128 + oc) * 30 + ky * 6 + kx] = pk2(v, v);
    }
}

// ==================================================================
// K1: fused 1x1 convs q/k/v (f32x2 pixel pairs)
// ==================================================================
__global__ void __launch_bounds__(256) k_qkv1x1(
    const float* __restrict__ x1, const float* __restrict__ x2,
    const float* __restrict__ bq, const float* __restrict__ bk, const float* __restrict__ bv)
{
    __shared__ __align__(16) ull s_x[64 * 32];
    __shared__ __align__(16) ull s_w[64 * 64];
    int t = threadIdx.x;
    int pp = t & 31, ch = t >> 5;
    long base = (long)blockIdx.x * 64;
    int b = (int)(base >> 16);
    int pix0 = (int)(base & 65535);
    int pixA = pix0 + 2 * pp;
    int parLo = ((pixA >> 8) + (pixA & 255)) & 1;

    const float* xb1 = x1 + ((long)b * 64) * 65536 + pix0;
    for (int i = t; i < 2048; i += 256) {
        int ic = i >> 5, p = i & 31;
        float2 v = *(const float2*)(xb1 + (long)ic * 65536 + 2 * p);
        s_x[i] = pk2(v.x, v.y);
    }
    for (int i = t; i < 4096; i += 256) s_w[i] = g_wq2[i];
    __syncthreads();

    ull acc[8];
#pragma unroll
    for (int o = 0; o < 8; o++) acc[o] = 0;
#pragma unroll 8
    for (int ic = 0; ic < 64; ic++) {
        ull xv = s_x[ic * 32 + pp];
        const ulonglong2* wv = (const ulonglong2*)(s_w + ic * 64 + ch * 8);
#pragma unroll
        for (int j = 0; j < 4; j++) {
            ulonglong2 w2 = wv[j];
            fma2(acc[2 * j], w2.x, xv);
            fma2(acc[2 * j + 1], w2.y, xv);
        }
    }
#pragma unroll
    for (int o = 0; o < 8; o++) {
        int oc = ch * 8 + o;
        float bias = bq[oc];
        float lo, hi; upk2(lo, hi, acc[o]);
        lo = (parLo == 0) ? lo + bias : bias;
        hi = (parLo == 1) ? hi + bias : bias;
        *(float2*)(g_tq + ((long)b * 64 + oc) * 65536 + pixA) = make_float2(lo, hi);
    }
    __syncthreads();
    for (int i = t; i < 4096; i += 256) s_w[i] = g_wk2[i];
    __syncthreads();
#pragma unroll
    for (int o = 0; o < 8; o++) acc[o] = 0;
#pragma unroll 8
    for (int ic = 0; ic < 64; ic++) {
        ull xv = s_x[ic * 32 + pp];
        const ulonglong2* wv = (const ulonglong2*)(s_w + ic * 64 + ch * 8);
#pragma unroll
        for (int j = 0; j < 4; j++) {
            ulonglong2 w2 = wv[j];
            fma2(acc[2 * j], w2.x, xv);
            fma2(acc[2 * j + 1], w2.y, xv);
        }
    }
#pragma unroll
    for (int o = 0; o < 8; o++) {
        int oc = ch * 8 + o;
        float bias = bk[oc];
        float lo, hi; upk2(lo, hi, acc[o]);
        lo = (parLo == 1) ? lo + bias : bias;
        hi = (parLo == 0) ? hi + bias : bias;
        *(float2*)(g_tk + ((long)b * 64 + oc) * 65536 + pixA) = make_float2(lo, hi);
    }
    __syncthreads();
    const float* xb2 = x2 + ((long)b * 64) * 65536 + pix0;
    for (int i = t; i < 2048; i += 256) {
        int ic = i >> 5, p = i & 31;
        float2 v = *(const float2*)(xb2 + (long)ic * 65536 + 2 * p);
        s_x[i] = pk2(v.x, v.y);
    }
    for (int i = t; i < 4096; i += 256) s_w[i] = g_wv2[i];
    __syncthreads();
#pragma unroll
    for (int o = 0; o < 8; o++) acc[o] = 0;
#pragma unroll 8
    for (int ic = 0; ic < 64; ic++) {
        ull xv = s_x[ic * 32 + pp];
        const ulonglong2* wv = (const ulonglong2*)(s_w + ic * 64 + ch * 8);
#pragma unroll
        for (int j = 0; j < 4; j++) {
            ulonglong2 w2 = wv[j];
            fma2(acc[2 * j], w2.x, xv);
            fma2(acc[2 * j + 1], w2.y, xv);
        }
    }
#pragma unroll
    for (int o = 0; o < 8; o++) {
        int oc = ch * 8 + o;
        float bias = bv[oc];
        float lo, hi; upk2(lo, hi, acc[o]);
        *(float2*)(g_tv + ((long)b * 64 + oc) * 65536 + pixA) = make_float2(lo + bias, hi + bias);
    }
}

// ==================================================================
// K2: depthwise 3x3 + parity squeeze, 8 rows per block
// ==================================================================
__global__ void __launch_bounds__(128) k_dw_squeeze(
    const float* __restrict__ q2w, const float* __restrict__ q2b,
    const float* __restrict__ k2w, const float* __restrict__ k2b,
    const float* __restrict__ v2w, const float* __restrict__ v2b)
{
    int r0 = blockIdx.x * 8;
    int bc = blockIdx.y;
    int c = bc & 63;
    int which = blockIdx.z;
    const float* src; const float* wz; const float* bz; float* dst; int pbase;
    if (which == 0)      { src = g_tq; wz = q2w; bz = q2b; dst = g_qs; pbase = 0; }
    else if (which == 1) { src = g_tk; wz = k2w; bz = k2b; dst = g_ks; pbase = 1; }
    else                 { src = g_tv; wz = v2w; bz = v2b; dst = g_vs; pbase = 1; }

    __shared__ float srow[10][258];
    const float* base = src + (long)bc * 65536;
    for (int i = threadIdx.x; i < 10 * 258; i += 128) {
        int row = i / 258, xx = i % 258;
        int yy = r0 - 1 + row, x = xx - 1;
        srow[row][xx] = (yy >= 0 && yy < 256 && x >= 0 && x < 256) ? base[yy * 256 + x] : 0.f;
    }
    __syncthreads();
    float w[9];
#pragma unroll
    for (int i = 0; i < 9; i++) w[i] = wz[c * 9 + i];
    float bias = bz[c];
    int cp = threadIdx.x;
#pragma unroll
    for (int rr = 0; rr < 8; rr++) {
        int r = r0 + rr;
        int joff = pbase ? (1 - (r & 1)) : (r & 1);
        int j = 2 * cp + joff;
        float acc = bias;
#pragma unroll
        for (int ky = 0; ky < 3; ky++)
#pragma unroll
            for (int kx = 0; kx < 3; kx++)
                acc += srow[rr + ky][j + kx] * w[ky * 3 + kx];
        dst[(long)bc * 32768 + r * 128 + cp] = acc;
    }
}

// ==================================================================
// K3: k softmax
// ==================================================================
__global__ void __launch_bounds__(256) k_ksoftmax()
{
    int bc = blockIdx.x;
    float* row = g_ks + (long)bc * 32768;
    __shared__ float red[256];
    int t = threadIdx.x;
    float m = -1e30f;
    for (int i = t; i < 32768; i += 256) m = fmaxf(m, row[i]);
    red[t] = m; __syncthreads();
    for (int s = 128; s > 0; s >>= 1) { if (t < s) red[t] = fmaxf(red[t], red[t + s]); __syncthreads(); }
    m = red[0]; __syncthreads();
    float sum = 0.f;
    for (int i = t; i < 32768; i += 256) sum += __expf(row[i] - m);
    red[t] = sum; __syncthreads();
    for (int s = 128; s > 0; s >>= 1) { if (t < s) red[t] += red[t + s]; __syncthreads(); }
    float inv = 1.0f / red[0];
    for (int i = t; i < 32768; i += 256) row[i] = __expf(row[i] - m) * inv;
}

// ==================================================================
// K4: ctx
// ==================================================================
__global__ void __launch_bounds__(256) k_zero_ctx()
{
    int i = blockIdx.x * 256 + threadIdx.x;
    if (i < BB * NHEAD * DD * DD) g_ctx[i] = 0.f;
}
__global__ void __launch_bounds__(256) k_ctx()
{
    __shared__ float sk[16][257];
    __shared__ float sv[16][257];
    int bh = blockIdx.x;
    int ch = blockIdx.y;
    int b = bh >> 2, h = bh & 3;
    long rowbase = ((long)b * 64 + h * 16) * 32768 + ch * 256;
    int t = threadIdx.x;
    for (int i = t; i < 16 * 256; i += 256) {
        int d = i >> 8, n = i & 255;
        sk[d][n] = g_ks[rowbase + (long)d * 32768 + n];
        sv[d][n] = g_vs[rowbase + (long)d * 32768 + n];
    }
    __syncthreads();
    int d = t >> 4, e = t & 15;
    float a = 0.f;
#pragma unroll 8
    for (int n = 0; n < 256; n++) a += sk[d][n] * sv[e][n];
    atomicAdd(&g_ctx[(bh << 8) + (d << 4) + e], a);
}

// ==================================================================
// K5: q softmax + ctx^T q + unsqueeze
// ==================================================================
__global__ void __launch_bounds__(128) k_att()
{
    int r = blockIdx.x, b = blockIdx.y;
    __shared__ float cs[NHEAD * DD * DD];
    int t = threadIdx.x;
    for (int i = t; i < NHEAD * DD * DD; i += 128) cs[i] = g_ctx[b * (NHEAD * DD * DD) + i];
    __syncthreads();
    int cp = t;
    float qv[64];
    const float* qbase = g_qs + (long)b * 64 * 32768 + r * 128 + cp;
#pragma unroll
    for (int c = 0; c < 64; c++) qv[c] = qbase[(long)c * 32768];
    int odd = r & 1;
    float2* out = (float2*)(g_att + ((long)b * 64) * 65536 + (long)r * 256) + cp;
#pragma unroll
    for (int h = 0; h < 4; h++) {
        float m = -1e30f;
#pragma unroll
        for (int d = 0; d < 16; d++) m = fmaxf(m, qv[h * 16 + d]);
        float s = 0.f;
#pragma unroll
        for (int d = 0; d < 16; d++) { float e = __expf(qv[h * 16 + d] - m); qv[h * 16 + d] = e; s += e; }
        float inv = 1.0f / s;
#pragma unroll
        for (int e = 0; e < 16; e++) {
            float a = 0.f;
#pragma unroll
            for (int d = 0; d < 16; d++) a += cs[h * 256 + d * 16 + e] * qv[h * 16 + d];
            a *= inv;
            int c = h * 16 + e;
            float2 v = odd ? make_float2(0.f, a) : make_float2(a, 0.f);
            out[(long)c * 32768] = v;
        }
    }
}

// ==================================================================
// K6: conv5x5 v2 (64->128). Warp-uniform oc (2 per warp, broadcast weights),
// contiguous 8-pair register tile per lane, conflict-free smem layout.
// block 256 = 8 warps. tile 8 rows x 64 px, 16 oc. grid (4, 32, B*8)
// lane: quad = lane>>3 (x chunk of 16 px), py = lane&7 (row)
// ==================================================================
#define C5_S   82          // ull row stride (2S mod 32 == 4 -> bank-tiled pys)
#define C5_NE  68          // staged pair-entries per row
#define C5_NIN (12*C5_NE)  // 816
#define C5_NW  480         // 16 oc * 30

__global__ void __launch_bounds__(256, 2) k_conv5x5(
    const float* __restrict__ rb, float* __restrict__ out)
{
    __shared__ __align__(16) ull s_in[2][12 * C5_S];
    __shared__ __align__(16) ull s_w[2][C5_NW];
    int t = threadIdx.x;
    int b = blockIdx.z >> 3, ocb = (blockIdx.z & 7) * 16;
    int y0 = blockIdx.y * 8, x0 = blockIdx.x * 64;
    int warp = t >> 5, lane = t & 31;
    int quad = lane >> 3, py = lane & 7;
    int o0 = ocb + 2 * warp;

    // ---- ic-invariant staging slots (4 per thread) ----
    int soff[4], sph[4];
    bool sv0[4], sv1[4], act[4];
#pragma unroll
    for (int s = 0; s < 4; s++) {
        int idx = t + s * 256;
        act[s] = idx < C5_NIN;
        int r = act[s] ? idx / C5_NE : 0;
        int e = act[s] ? idx - r * C5_NE : 0;
        int gy = y0 - 2 + r, gx = x0 - 2 + e;
        bool yok = (gy >= 0 && gy < 256);
        sv0[s] = act[s] && yok && gx >= 0 && gx < 256;
        sv1[s] = act[s] && yok && (gx + 1) >= 0 && (gx + 1) < 256;
        soff[s] = gy * 256 + gx;
        sph[s] = r * C5_S + e;
    }
    bool hasW2 = (t + 256) < C5_NW;
    long wb0 = (long)ocb * 30 + t;

    const float* inb = g_att + (long)b * 64 * 65536;
    float bv0 = rb[o0], bv1 = rb[o0 + 1];
    ull accA[8], accB[8];
#pragma unroll
    for (int p = 0; p < 8; p++) { accA[p] = pk2(bv0, bv0); accB[p] = pk2(bv1, bv1); }

    // ---- prologue: stage ic=0 ----
#pragma unroll
    for (int s = 0; s < 4; s++)
        if (act[s]) {
            const float* p = inb + soff[s];
            s_in[0][sph[s]] = pk2(sv0[s] ? p[0] : 0.f, sv1[s] ? p[1] : 0.f);
        }
    s_w[0][t] = g_rw2[wb0];
    if (hasW2) s_w[0][t + 256] = g_rw2[wb0 + 256];
    __syncthreads();

    for (int ic = 0; ic < 64; ic++) {
        int cur = ic & 1;
        // prefetch next ic into registers
        ull pv[4]; ull w0v = 0, w1v = 0;
        if (ic < 63) {
#pragma unroll
            for (int s = 0; s < 4; s++) {
                if (act[s]) {
                    const float* p = inb + (long)(ic + 1) * 65536 + soff[s];
                    pv[s] = pk2(sv0[s] ? p[0] : 0.f, sv1[s] ? p[1] : 0.f);
                } else pv[s] = 0;
            }
            long wb = (long)(ic + 1) * (128 * 30) + wb0;
            w0v = g_rw2[wb];
            if (hasW2) w1v = g_rw2[wb + 256];
        }

        const ull* wp0 = s_w[cur] + 2 * warp * 30;
        const ull* wp1 = wp0 + 30;
#pragma unroll 1
        for (int ky = 0; ky < 5; ky++) {
            const ull* basep = s_in[cur] + (py + ky) * C5_S + quad * 16;
            ulonglong2 a01 = *(const ulonglong2*)(wp0 + ky * 6);
            ulonglong2 a23 = *(const ulonglong2*)(wp0 + ky * 6 + 2);
            ull a4 = wp0[ky * 6 + 4];
            ulonglong2 b01 = *(const ulonglong2*)(wp1 + ky * 6);
            ulonglong2 b23 = *(const ulonglong2*)(wp1 + ky * 6 + 2);
            ull b4 = wp1[ky * 6 + 4];
            ull wA[5] = {a01.x, a01.y, a23.x, a23.y, a4};
            ull wB[5] = {b01.x, b01.y, b23.x, b23.y, b4};

            // chunk 1: pairs 0..3 need entries 0..10
            {
                ull win[12];
#pragma unroll
                for (int m = 0; m < 6; m++) {
                    ulonglong2 v = *(const ulonglong2*)(basep + 2 * m);
                    win[2 * m] = v.x; win[2 * m + 1] = v.y;
                }
#pragma unroll
                for (int p = 0; p < 4; p++)
#pragma unroll
                    for (int kx = 0; kx < 5; kx++) {
                        fma2(accA[p], wA[kx], win[2 * p + kx]);
                        fma2(accB[p], wB[kx], win[2 * p + kx]);
                    }
            }
            // chunk 2: pairs 4..7 need entries 8..18
            {
                ull win[12];
#pragma unroll
                for (int m = 0; m < 6; m++) {
                    ulonglong2 v = *(const ulonglong2*)(basep + 8 + 2 * m);
                    win[2 * m] = v.x; win[2 * m + 1] = v.y;
                }
#pragma unroll
                for (int p = 4; p < 8; p++)
#pragma unroll
                    for (int kx = 0; kx < 5; kx++) {
                        fma2(accA[p], wA[kx], win[2 * p + kx - 8]);
                        fma2(accB[p], wB[kx], win[2 * p + kx - 8]);
                    }
            }
        }

        if (ic < 63) {
            int nxt = cur ^ 1;
#pragma unroll
            for (int s = 0; s < 4; s++)
                if (act[s]) s_in[nxt][sph[s]] = pv[s];
            s_w[nxt][t] = w0v;
            if (hasW2) s_w[nxt][t + 256] = w1v;
        }
        __syncthreads();
    }

    long base0 = ((long)b * 128 + o0) * 65536 + (long)(y0 + py) * 256 + x0 + quad * 16;
#pragma unroll
    for (int p = 0; p < 8; p++) {
        float lo, hi;
        upk2(lo, hi, accA[p]);
        *(float2*)(out + base0 + 2 * p) = make_float2(lo, hi);
        upk2(lo, hi, accB[p]);
        *(float2*)(out + base0 + 65536 + 2 * p) = make_float2(lo, hi);
    }
}

// ==================================================================
// K7: m1 = gelu(conv1x1 128->256) packed (R3 version)
// ==================================================================
__global__ void __launch_bounds__(128) k_m1(
    const float* __restrict__ att, const float* __restrict__ bias)
{
    __shared__ __align__(16) float sbuf[8448];
    __shared__ __align__(16) float s_wT[2048];
    int t = threadIdx.x;
    long pix0 = (long)blockIdx.x * 32;
    int b = (int)(pix0 >> 16);
    int pp0 = (int)(pix0 & 65535);
    const float* ab = att + ((long)b * 128) * 65536 + pp0;
#pragma unroll 4
    for (int i = t; i < 4096; i += 128) {
        int ic = i >> 5, p = i & 31;
        sbuf[i] = ab[(long)ic * 65536 + p];
    }
    int oc0 = 2 * t;
    float b0 = bias[oc0], b1 = bias[oc0 + 1];
    ull acc0[16], acc1[16];
#pragma unroll
    for (int j = 0; j < 16; j++) { acc0[j] = pk2(b0, b0); acc1[j] = pk2(b1, b1); }

    for (int c8 = 0; c8 < 128; c8 += 8) {
        __syncthreads();
        for (int i = t; i < 512; i += 128)
            *(float4*)(s_wT + i * 4) = *(const float4*)(g_w1T + c8 * 256 + i * 4);
        __syncthreads();
#pragma unroll
        for (int k = 0; k < 8; k++) {
            ull wp = *(const ull*)(s_wT + k * 256 + oc0);
            float f0, f1; upk2(f0, f1, wp);
            ull w2a = pk2(f0, f0), w2b = pk2(f1, f1);
            const ulonglong2* xr = (const ulonglong2*)(sbuf + (c8 + k) * 32);
#pragma unroll
            for (int j = 0; j < 8; j++) {
                ulonglong2 x2 = xr[j];
                fma2(acc0[2 * j],     w2a, x2.x); fma2(acc0[2 * j + 1], w2a, x2.y);
                fma2(acc1[2 * j],     w2b, x2.x); fma2(acc1[2 * j + 1], w2b, x2.y);
            }
        }
    }
    __syncthreads();
#pragma unroll
    for (int j = 0; j < 16; j++) {
        float lo, hi;
        upk2(lo, hi, acc0[j]);
        sbuf[oc0 * 33 + 2 * j]     = gelu_f(lo);
        sbuf[oc0 * 33 + 2 * j + 1] = gelu_f(hi);
        upk2(lo, hi, acc1[j]);
        sbuf[(oc0 + 1) * 33 + 2 * j]     = gelu_f(lo);
        sbuf[(oc0 + 1) * 33 + 2 * j + 1] = gelu_f(hi);
    }
    __syncthreads();
    float* ob = g_m1 + ((long)b * 256) * 65536 + pp0;
#pragma unroll 4
    for (int i = t; i < 8192; i += 128) {
        int o = i >> 5, p = i & 31;
        ob[(long)o * 65536 + p] = sbuf[o * 33 + p];
    }
}

// ==================================================================
// K8: m2 = gelu(depthwise 3x3, 256 ch), 8 rows per block
// ==================================================================
__global__ void __launch_bounds__(256) k_m2(
    const float* __restrict__ w, const float* __restrict__ bias)
{
    int r0 = blockIdx.x * 8;
    int bc = blockIdx.y;
    int c = bc & 255;
    const float* base = g_m1 + (long)bc * 65536;
    __shared__ float srow[10][258];
    for (int i = threadIdx.x; i < 10 * 258; i += 256) {
        int row = i / 258, xx = i % 258;
        int yy = r0 - 1 + row, x = xx - 1;
        srow[row][xx] = (yy >= 0 && yy < 256 && x >= 0 && x < 256) ? base[yy * 256 + x] : 0.f;
    }
    __syncthreads();
    float wl[9];
#pragma unroll
    for (int i = 0; i < 9; i++) wl[i] = w[c * 9 + i];
    float bv = bias[c];
    int x = threadIdx.x;
#pragma unroll
    for (int rr = 0; rr < 8; rr++) {
        float acc = bv;
#pragma unroll
        for (int ky = 0; ky < 3; ky++)
#pragma unroll
            for (int kx = 0; kx < 3; kx++)
                acc += srow[rr + ky][x + kx] * wl[ky * 3 + kx];
        g_m2[(long)bc * 65536 + (long)(r0 + rr) * 256 + x] = gelu_f(acc);
    }
}

// ==================================================================
// K9: out += conv1x1(m2, 256->128) packed (R3 version)
// ==================================================================
__global__ void __launch_bounds__(64) k_m3(
    float* __restrict__ out, const float* __restrict__ bias)
{
    __shared__ __align__(16) float sbuf[8448];
    __shared__ __align__(16) float s_wT[1024];
    int t = threadIdx.x;
    long pix0 = (long)blockIdx.x * 32;
    int b = (int)(pix0 >> 16);
    int pp0 = (int)(pix0 & 65535);
    const float* ib = g_m2 + ((long)b * 256) * 65536 + pp0;
#pragma unroll 8
    for (int i = t; i < 8192; i += 64) {
        int ic = i >> 5, p = i & 31;
        sbuf[i] = ib[(long)ic * 65536 + p];
    }
    int oc0 = 2 * t;
    float b0 = bias[oc0], b1 = bias[oc0 + 1];
    ull acc0[16], acc1[16];
#pragma unroll
    for (int j = 0; j < 16; j++) { acc0[j] = pk2(b0, b0); acc1[j] = pk2(b1, b1); }

    for (int c8 = 0; c8 < 256; c8 += 8) {
        __syncthreads();
        for (int i = t; i < 256; i += 64)
            *(float4*)(s_wT + i * 4) = *(const float4*)(g_w3T + c8 * 128 + i * 4);
        __syncthreads();
#pragma unroll
        for (int k = 0; k < 8; k++) {
            ull wp = *(const ull*)(s_wT + k * 128 + oc0);
            float f0, f1; upk2(f0, f1, wp);
            ull w2a = pk2(f0, f0), w2b = pk2(f1, f1);
            const ulonglong2* xr = (const ulonglong2*)(sbuf + (c8 + k) * 32);
#pragma unroll
            for (int j = 0; j < 8; j++) {
                ulonglong2 x2 = xr[j];
                fma2(acc0[2 * j],     w2a, x2.x); fma2(acc0[2 * j + 1], w2a, x2.y);
                fma2(acc1[2 * j],     w2b, x2.x); fma2(acc1[2 * j + 1], w2b, x2.y);
            }
        }
    }
    __syncthreads();
#pragma unroll
    for (int j = 0; j < 16; j++) {
        float lo, hi;
        upk2(lo, hi, acc0[j]);
        sbuf[oc0 * 33 + 2 * j]     = lo;
        sbuf[oc0 * 33 + 2 * j + 1] = hi;
        upk2(lo, hi, acc1[j]);
        sbuf[(oc0 + 1) * 33 + 2 * j]     = lo;
        sbuf[(oc0 + 1) * 33 + 2 * j + 1] = hi;
    }
    __syncthreads();
    float* ob = out + ((long)b * 128) * 65536 + pp0;
#pragma unroll 8
    for (int i = t; i < 4096; i += 64) {
        int o = i >> 5, p = i & 31;
        long a = (long)o * 65536 + p;
        ob[a] = ob[a] + sbuf[o * 33 + p];
    }
}

// ==================================================================
extern "C" void kernel_launch(void* const* d_in, const int* in_sizes, int n_in,
                              void* d_out, int out_size)
{
    const float* x1  = (const float*)d_in[0];
    const float* x2  = (const float*)d_in[1];
    const float* q1w = (const float*)d_in[2];  const float* q1b = (const float*)d_in[3];
    const float* q2w = (const float*)d_in[4];  const float* q2b = (const float*)d_in[5];
    const float* k1w = (const float*)d_in[6];  const float* k1b = (const float*)d_in[7];
    const float* k2w = (const float*)d_in[8];  const float* k2b = (const float*)d_in[9];
    const float* v1w = (const float*)d_in[10]; const float* v1b = (const float*)d_in[11];
    const float* v2w = (const float*)d_in[12]; const float* v2b = (const float*)d_in[13];
    const float* rw  = (const float*)d_in[14]; const float* rb  = (const float*)d_in[15];
    const float* m1w = (const float*)d_in[16]; const float* m1b = (const float*)d_in[17];
    const float* m2w = (const float*)d_in[18]; const float* m2b = (const float*)d_in[19];
    const float* m3w = (const float*)d_in[20]; const float* m3b = (const float*)d_in[21];
    float* out = (float*)d_out;

    void* tq_addr = nullptr;
    cudaGetSymbolAddress(&tq_addr, g_tq);

    k_prep<<<800, 256>>>(m1w, m3w, rw, q1w, k1w, v1w);                     // idx 0
    k_qkv1x1<<<4096, 256>>>(x1, x2, q1b, k1b, v1b);                        // idx 1
    k_dw_squeeze<<<dim3(32, 256, 3), 128>>>(q2w, q2b, k2w, k2b, v2w, v2b); // idx 2
    // profiling probe (ncu captures idx 3): quarter-grid conv v2 to dead g_tq
    k_conv5x5<<<dim3(1, 32, 32), 256>>>(rb, (float*)tq_addr);              // idx 3
    k_ksoftmax<<<256, 256>>>();                                            // idx 4
    k_zero_ctx<<<16, 256>>>();                                             // idx 5
    k_ctx<<<dim3(16, 128), 256>>>();                                       // idx 6
    k_att<<<dim3(256, 4), 128>>>();                                        // idx 7
    k_conv5x5<<<dim3(4, 32, 32), 256>>>(rb, out);                          // idx 8
    k_m1<<<8192, 128>>>(out, m1b);                                         // idx 9
    k_m2<<<dim3(32, 1024), 256>>>(m2w, m2b);                               // idx 10
    k_m3<<<8192, 64>>>(out, m3b);                                          // idx 11
}

// round 6
// speedup vs baseline: 1.5916x; 1.0989x over previous
#include <cuda_runtime.h>
#include <math.h>

typedef unsigned long long ull;

// ---------------- problem constants ----------------
#define BB    4
#define CC    64
#define HH    256
#define WW    256
#define NPIX  65536
#define NSQ   32768
#define NHEAD 4
#define DD    16

// ---------------- scratch ----------------
__device__ float g_tq[BB * CC * NPIX];
__device__ float g_tk[BB * CC * NPIX];
__device__ float g_tv[BB * CC * NPIX];
__device__ float g_qs[BB * CC * NSQ];
__device__ float g_ks[BB * CC * NSQ];
__device__ float g_vs[BB * CC * NSQ];
__device__ float g_ctx[BB * NHEAD * DD * DD];
__device__ float g_att[BB * CC * NPIX];
__device__ float g_m1[BB * 4 * CC * NPIX];
__device__ float g_m2[BB * 4 * CC * NPIX];
__device__ __align__(16) float g_w1T[128 * 256];
__device__ __align__(16) float g_w3T[256 * 128];
__device__ __align__(16) ull   g_rw2[64 * 128 * 30];
__device__ __align__(16) ull   g_wq2[64 * 64];
__device__ __align__(16) ull   g_wk2[64 * 64];
__device__ __align__(16) ull   g_wv2[64 * 64];

// ---------------- f32x2 helpers ----------------
__device__ __forceinline__ ull pk2(float lo, float hi) {
    ull r; asm("mov.b64 %0,{%1,%2};" : "=l"(r) : "f"(lo), "f"(hi)); return r;
}
__device__ __forceinline__ void upk2(float& lo, float& hi, ull v) {
    asm("mov.b64 {%0,%1},%2;" : "=f"(lo), "=f"(hi) : "l"(v));
}
__device__ __forceinline__ void fma2(ull& d, ull a, ull b) {
    asm("fma.rn.f32x2 %0,%1,%2,%0;" : "+l"(d) : "l"(a), "l"(b));
}
__device__ __forceinline__ float gelu_f(float x) {
    return 0.5f * x * (1.0f + erff(x * 0.7071067811865476f));
}

// ==================================================================
// K0: prepack
// ==================================================================
__global__ void __launch_bounds__(256) k_prep(
    const float* __restrict__ m1w, const float* __restrict__ m3w, const float* __restrict__ rw,
    const float* __restrict__ q1w, const float* __restrict__ k1w, const float* __restrict__ v1w)
{
    int i = blockIdx.x * 256 + threadIdx.x;
    if (i < 32768) {
        { int oc = i >> 7, ic = i & 127; g_w1T[ic * 256 + oc] = m1w[i]; }
        { int oc = i >> 8, ic = i & 255; g_w3T[ic * 128 + oc] = m3w[i]; }
    }
    if (i < 4096) {
        int oc = i >> 6, ic = i & 63;
        float v;
        v = q1w[i]; g_wq2[ic * 64 + oc] = pk2(v, v);
        v = k1w[i]; g_wk2[ic * 64 + oc] = pk2(v, v);
        v = v1w[i]; g_wv2[ic * 64 + oc] = pk2(v, v);
    }
    if (i < 204800) {
        int k = i % 25; int rest = i / 25;
        int ic = rest & 63, oc = rest >> 6;
        int ky = k / 5, kx = k - ky * 5;
        float v = rw[i];
        g_rw2[((long)ic * 128 + oc) * 30 + ky * 6 + kx] = pk2(v, v);
    }
}

// ==================================================================
// K1: fused 1x1 convs q/k/v (f32x2 pixel pairs)
// ==================================================================
__global__ void __launch_bounds__(256) k_qkv1x1(
    const float* __restrict__ x1, const float* __restrict__ x2,
    const float* __restrict__ bq, const float* __restrict__ bk, const float* __restrict__ bv)
{
    __shared__ __align__(16) ull s_x[64 * 32];
    __shared__ __align__(16) ull s_w[64 * 64];
    int t = threadIdx.x;
    int pp = t & 31, ch = t >> 5;
    long base = (long)blockIdx.x * 64;
    int b = (int)(base >> 16);
    int pix0 = (int)(base & 65535);
    int pixA = pix0 + 2 * pp;
    int parLo = ((pixA >> 8) + (pixA & 255)) & 1;

    const float* xb1 = x1 + ((long)b * 64) * 65536 + pix0;
    for (int i = t; i < 2048; i += 256) {
        int ic = i >> 5, p = i & 31;
        float2 v = *(const float2*)(xb1 + (long)ic * 65536 + 2 * p);
        s_x[i] = pk2(v.x, v.y);
    }
    for (int i = t; i < 4096; i += 256) s_w[i] = g_wq2[i];
    __syncthreads();

    ull acc[8];
#pragma unroll
    for (int o = 0; o < 8; o++) acc[o] = 0;
#pragma unroll 8
    for (int ic = 0; ic < 64; ic++) {
        ull xv = s_x[ic * 32 + pp];
        const ulonglong2* wv = (const ulonglong2*)(s_w + ic * 64 + ch * 8);
#pragma unroll
        for (int j = 0; j < 4; j++) {
            ulonglong2 w2 = wv[j];
            fma2(acc[2 * j], w2.x, xv);
            fma2(acc[2 * j + 1], w2.y, xv);
        }
    }
#pragma unroll
    for (int o = 0; o < 8; o++) {
        int oc = ch * 8 + o;
        float bias = bq[oc];
        float lo, hi; upk2(lo, hi, acc[o]);
        lo = (parLo == 0) ? lo + bias : bias;
        hi = (parLo == 1) ? hi + bias : bias;
        *(float2*)(g_tq + ((long)b * 64 + oc) * 65536 + pixA) = make_float2(lo, hi);
    }
    __syncthreads();
    for (int i = t; i < 4096; i += 256) s_w[i] = g_wk2[i];
    __syncthreads();
#pragma unroll
    for (int o = 0; o < 8; o++) acc[o] = 0;
#pragma unroll 8
    for (int ic = 0; ic < 64; ic++) {
        ull xv = s_x[ic * 32 + pp];
        const ulonglong2* wv = (const ulonglong2*)(s_w + ic * 64 + ch * 8);
#pragma unroll
        for (int j = 0; j < 4; j++) {
            ulonglong2 w2 = wv[j];
            fma2(acc[2 * j], w2.x, xv);
            fma2(acc[2 * j + 1], w2.y, xv);
        }
    }
#pragma unroll
    for (int o = 0; o < 8; o++) {
        int oc = ch * 8 + o;
        float bias = bk[oc];
        float lo, hi; upk2(lo, hi, acc[o]);
        lo = (parLo == 1) ? lo + bias : bias;
        hi = (parLo == 0) ? hi + bias : bias;
        *(float2*)(g_tk + ((long)b * 64 + oc) * 65536 + pixA) = make_float2(lo, hi);
    }
    __syncthreads();
    const float* xb2 = x2 + ((long)b * 64) * 65536 + pix0;
    for (int i = t; i < 2048; i += 256) {
        int ic = i >> 5, p = i & 31;
        float2 v = *(const float2*)(xb2 + (long)ic * 65536 + 2 * p);
        s_x[i] = pk2(v.x, v.y);
    }
    for (int i = t; i < 4096; i += 256) s_w[i] = g_wv2[i];
    __syncthreads();
#pragma unroll
    for (int o = 0; o < 8; o++) acc[o] = 0;
#pragma unroll 8
    for (int ic = 0; ic < 64; ic++) {
        ull xv = s_x[ic * 32 + pp];
        const ulonglong2* wv = (const ulonglong2*)(s_w + ic * 64 + ch * 8);
#pragma unroll
        for (int j = 0; j < 4; j++) {
            ulonglong2 w2 = wv[j];
            fma2(acc[2 * j], w2.x, xv);
            fma2(acc[2 * j + 1], w2.y, xv);
        }
    }
#pragma unroll
    for (int o = 0; o < 8; o++) {
        int oc = ch * 8 + o;
        float bias = bv[oc];
        float lo, hi; upk2(lo, hi, acc[o]);
        *(float2*)(g_tv + ((long)b * 64 + oc) * 65536 + pixA) = make_float2(lo + bias, hi + bias);
    }
}

// ==================================================================
// K2: depthwise 3x3 + parity squeeze, 8 rows per block
// ==================================================================
__global__ void __launch_bounds__(128) k_dw_squeeze(
    const float* __restrict__ q2w, const float* __restrict__ q2b,
    const float* __restrict__ k2w, const float* __restrict__ k2b,
    const float* __restrict__ v2w, const float* __restrict__ v2b)
{
    int r0 = blockIdx.x * 8;
    int bc = blockIdx.y;
    int c = bc & 63;
    int which = blockIdx.z;
    const float* src; const float* wz; const float* bz; float* dst; int pbase;
    if (which == 0)      { src = g_tq; wz = q2w; bz = q2b; dst = g_qs; pbase = 0; }
    else if (which == 1) { src = g_tk; wz = k2w; bz = k2b; dst = g_ks; pbase = 1; }
    else                 { src = g_tv; wz = v2w; bz = v2b; dst = g_vs; pbase = 1; }

    __shared__ float srow[10][258];
    const float* base = src + (long)bc * 65536;
    for (int i = threadIdx.x; i < 10 * 258; i += 128) {
        int row = i / 258, xx = i % 258;
        int yy = r0 - 1 + row, x = xx - 1;
        srow[row][xx] = (yy >= 0 && yy < 256 && x >= 0 && x < 256) ? base[yy * 256 + x] : 0.f;
    }
    __syncthreads();
    float w[9];
#pragma unroll
    for (int i = 0; i < 9; i++) w[i] = wz[c * 9 + i];
    float bias = bz[c];
    int cp = threadIdx.x;
#pragma unroll
    for (int rr = 0; rr < 8; rr++) {
        int r = r0 + rr;
        int joff = pbase ? (1 - (r & 1)) : (r & 1);
        int j = 2 * cp + joff;
        float acc = bias;
#pragma unroll
        for (int ky = 0; ky < 3; ky++)
#pragma unroll
            for (int kx = 0; kx < 3; kx++)
                acc += srow[rr + ky][j + kx] * w[ky * 3 + kx];
        dst[(long)bc * 32768 + r * 128 + cp] = acc;
    }
}

// ==================================================================
// K3: k softmax
// ==================================================================
__global__ void __launch_bounds__(256) k_ksoftmax()
{
    int bc = blockIdx.x;
    float* row = g_ks + (long)bc * 32768;
    __shared__ float red[256];
    int t = threadIdx.x;
    float m = -1e30f;
    for (int i = t; i < 32768; i += 256) m = fmaxf(m, row[i]);
    red[t] = m; __syncthreads();
    for (int s = 128; s > 0; s >>= 1) { if (t < s) red[t] = fmaxf(red[t], red[t + s]); __syncthreads(); }
    m = red[0]; __syncthreads();
    float sum = 0.f;
    for (int i = t; i < 32768; i += 256) sum += __expf(row[i] - m);
    red[t] = sum; __syncthreads();
    for (int s = 128; s > 0; s >>= 1) { if (t < s) red[t] += red[t + s]; __syncthreads(); }
    float inv = 1.0f / red[0];
    for (int i = t; i < 32768; i += 256) row[i] = __expf(row[i] - m) * inv;
}

// ==================================================================
// K4: ctx
// ==================================================================
__global__ void __launch_bounds__(256) k_zero_ctx()
{
    int i = blockIdx.x * 256 + threadIdx.x;
    if (i < BB * NHEAD * DD * DD) g_ctx[i] = 0.f;
}
__global__ void __launch_bounds__(256) k_ctx()
{
    __shared__ float sk[16][257];
    __shared__ float sv[16][257];
    int bh = blockIdx.x;
    int ch = blockIdx.y;
    int b = bh >> 2, h = bh & 3;
    long rowbase = ((long)b * 64 + h * 16) * 32768 + ch * 256;
    int t = threadIdx.x;
    for (int i = t; i < 16 * 256; i += 256) {
        int d = i >> 8, n = i & 255;
        sk[d][n] = g_ks[rowbase + (long)d * 32768 + n];
        sv[d][n] = g_vs[rowbase + (long)d * 32768 + n];
    }
    __syncthreads();
    int d = t >> 4, e = t & 15;
    float a = 0.f;
#pragma unroll 8
    for (int n = 0; n < 256; n++) a += sk[d][n] * sv[e][n];
    atomicAdd(&g_ctx[(bh << 8) + (d << 4) + e], a);
}

// ==================================================================
// K5: q softmax + ctx^T q + unsqueeze
// ==================================================================
__global__ void __launch_bounds__(128) k_att()
{
    int r = blockIdx.x, b = blockIdx.y;
    __shared__ float cs[NHEAD * DD * DD];
    int t = threadIdx.x;
    for (int i = t; i < NHEAD * DD * DD; i += 128) cs[i] = g_ctx[b * (NHEAD * DD * DD) + i];
    __syncthreads();
    int cp = t;
    float qv[64];
    const float* qbase = g_qs + (long)b * 64 * 32768 + r * 128 + cp;
#pragma unroll
    for (int c = 0; c < 64; c++) qv[c] = qbase[(long)c * 32768];
    int odd = r & 1;
    float2* out = (float2*)(g_att + ((long)b * 64) * 65536 + (long)r * 256) + cp;
#pragma unroll
    for (int h = 0; h < 4; h++) {
        float m = -1e30f;
#pragma unroll
        for (int d = 0; d < 16; d++) m = fmaxf(m, qv[h * 16 + d]);
        float s = 0.f;
#pragma unroll
        for (int d = 0; d < 16; d++) { float e = __expf(qv[h * 16 + d] - m); qv[h * 16 + d] = e; s += e; }
        float inv = 1.0f / s;
#pragma unroll
        for (int e = 0; e < 16; e++) {
            float a = 0.f;
#pragma unroll
            for (int d = 0; d < 16; d++) a += cs[h * 256 + d * 16 + e] * qv[h * 16 + d];
            a *= inv;
            int c = h * 16 + e;
            float2 v = odd ? make_float2(0.f, a) : make_float2(a, 0.f);
            out[(long)c * 32768] = v;
        }
    }
}

// ==================================================================
// K6: conv5x5 v3. Like v2 but chunk2 reuses e[8..11] registers -> 10 LDS128/ky.
// ==================================================================
#define C5_S   82
#define C5_NE  68
#define C5_NIN (12*C5_NE)
#define C5_NW  480

__global__ void __launch_bounds__(256, 2) k_conv5x5(
    const float* __restrict__ rb, float* __restrict__ out)
{
    __shared__ __align__(16) ull s_in[2][12 * C5_S];
    __shared__ __align__(16) ull s_w[2][C5_NW];
    int t = threadIdx.x;
    int b = blockIdx.z >> 3, ocb = (blockIdx.z & 7) * 16;
    int y0 = blockIdx.y * 8, x0 = blockIdx.x * 64;
    int warp = t >> 5, lane = t & 31;
    int quad = lane >> 3, py = lane & 7;
    int o0 = ocb + 2 * warp;

    int soff[4], sph[4];
    bool sv0[4], sv1[4], act[4];
#pragma unroll
    for (int s = 0; s < 4; s++) {
        int idx = t + s * 256;
        act[s] = idx < C5_NIN;
        int r = act[s] ? idx / C5_NE : 0;
        int e = act[s] ? idx - r * C5_NE : 0;
        int gy = y0 - 2 + r, gx = x0 - 2 + e;
        bool yok = (gy >= 0 && gy < 256);
        sv0[s] = act[s] && yok && gx >= 0 && gx < 256;
        sv1[s] = act[s] && yok && (gx + 1) >= 0 && (gx + 1) < 256;
        soff[s] = gy * 256 + gx;
        sph[s] = r * C5_S + e;
    }
    bool hasW2 = (t + 256) < C5_NW;
    long wb0 = (long)ocb * 30 + t;

    const float* inb = g_att + (long)b * 64 * 65536;
    float bv0 = rb[o0], bv1 = rb[o0 + 1];
    ull accA[8], accB[8];
#pragma unroll
    for (int p = 0; p < 8; p++) { accA[p] = pk2(bv0, bv0); accB[p] = pk2(bv1, bv1); }

#pragma unroll
    for (int s = 0; s < 4; s++)
        if (act[s]) {
            const float* p = inb + soff[s];
            s_in[0][sph[s]] = pk2(sv0[s] ? p[0] : 0.f, sv1[s] ? p[1] : 0.f);
        }
    s_w[0][t] = g_rw2[wb0];
    if (hasW2) s_w[0][t + 256] = g_rw2[wb0 + 256];
    __syncthreads();

    for (int ic = 0; ic < 64; ic++) {
        int cur = ic & 1;
        ull pv[4]; ull w0v = 0, w1v = 0;
        if (ic < 63) {
#pragma unroll
            for (int s = 0; s < 4; s++) {
                if (act[s]) {
                    const float* p = inb + (long)(ic + 1) * 65536 + soff[s];
                    pv[s] = pk2(sv0[s] ? p[0] : 0.f, sv1[s] ? p[1] : 0.f);
                } else pv[s] = 0;
            }
            long wb = (long)(ic + 1) * (128 * 30) + wb0;
            w0v = g_rw2[wb];
            if (hasW2) w1v = g_rw2[wb + 256];
        }

        const ull* wp0 = s_w[cur] + 2 * warp * 30;
        const ull* wp1 = wp0 + 30;
#pragma unroll 1
        for (int ky = 0; ky < 5; ky++) {
            const ull* basep = s_in[cur] + (py + ky) * C5_S + quad * 16;
            ulonglong2 a01 = *(const ulonglong2*)(wp0 + ky * 6);
            ulonglong2 a23 = *(const ulonglong2*)(wp0 + ky * 6 + 2);
            ull a4 = wp0[ky * 6 + 4];
            ulonglong2 b01 = *(const ulonglong2*)(wp1 + ky * 6);
            ulonglong2 b23 = *(const ulonglong2*)(wp1 + ky * 6 + 2);
            ull b4 = wp1[ky * 6 + 4];
            ull wA[5] = {a01.x, a01.y, a23.x, a23.y, a4};
            ull wB[5] = {b01.x, b01.y, b23.x, b23.y, b4};

            // chunk 1: entries 0..11, pairs 0..3
            ull e[12];
#pragma unroll
            for (int m = 0; m < 6; m++) {
                ulonglong2 v = *(const ulonglong2*)(basep + 2 * m);
                e[2 * m] = v.x; e[2 * m + 1] = v.y;
            }
#pragma unroll
            for (int p = 0; p < 4; p++)
#pragma unroll
                for (int kx = 0; kx < 5; kx++) {
                    fma2(accA[p], wA[kx], e[2 * p + kx]);
                    fma2(accB[p], wB[kx], e[2 * p + kx]);
                }
            // chunk 2: entries 12..19 fresh, reuse e[8..11]
            ull f[8];
#pragma unroll
            for (int m = 0; m < 4; m++) {
                ulonglong2 v = *(const ulonglong2*)(basep + 12 + 2 * m);
                f[2 * m] = v.x; f[2 * m + 1] = v.y;
            }
#pragma unroll
            for (int p = 4; p < 8; p++)
#pragma unroll
                for (int kx = 0; kx < 5; kx++) {
                    int idx = 2 * p + kx;          // 8..19 (compile-time)
                    ull xv = (idx < 12) ? e[idx] : f[idx - 12];
                    fma2(accA[p], wA[kx], xv);
                    fma2(accB[p], wB[kx], xv);
                }
        }

        if (ic < 63) {
            int nxt = cur ^ 1;
#pragma unroll
            for (int s = 0; s < 4; s++)
                if (act[s]) s_in[nxt][sph[s]] = pv[s];
            s_w[nxt][t] = w0v;
            if (hasW2) s_w[nxt][t + 256] = w1v;
        }
        __syncthreads();
    }

    long base0 = ((long)b * 128 + o0) * 65536 + (long)(y0 + py) * 256 + x0 + quad * 16;
#pragma unroll
    for (int p = 0; p < 8; p++) {
        float lo, hi;
        upk2(lo, hi, accA[p]);
        *(float2*)(out + base0 + 2 * p) = make_float2(lo, hi);
        upk2(lo, hi, accB[p]);
        *(float2*)(out + base0 + 65536 + 2 * p) = make_float2(lo, hi);
    }
}

// ==================================================================
// K7: m1 = gelu(conv1x1 128->256)
// ==================================================================
__global__ void __launch_bounds__(128) k_m1(
    const float* __restrict__ att, const float* __restrict__ bias)
{
    __shared__ __align__(16) float sbuf[8448];
    __shared__ __align__(16) float s_wT[2048];
    int t = threadIdx.x;
    long pix0 = (long)blockIdx.x * 32;
    int b = (int)(pix0 >> 16);
    int pp0 = (int)(pix0 & 65535);
    const float* ab = att + ((long)b * 128) * 65536 + pp0;
#pragma unroll 4
    for (int i = t; i < 4096; i += 128) {
        int ic = i >> 5, p = i & 31;
        sbuf[i] = ab[(long)ic * 65536 + p];
    }
    int oc0 = 2 * t;
    float b0 = bias[oc0], b1 = bias[oc0 + 1];
    ull acc0[16], acc1[16];
#pragma unroll
    for (int j = 0; j < 16; j++) { acc0[j] = pk2(b0, b0); acc1[j] = pk2(b1, b1); }

    for (int c8 = 0; c8 < 128; c8 += 8) {
        __syncthreads();
        for (int i = t; i < 512; i += 128)
            *(float4*)(s_wT + i * 4) = *(const float4*)(g_w1T + c8 * 256 + i * 4);
        __syncthreads();
#pragma unroll
        for (int k = 0; k < 8; k++) {
            ull wp = *(const ull*)(s_wT + k * 256 + oc0);
            float f0, f1; upk2(f0, f1, wp);
            ull w2a = pk2(f0, f0), w2b = pk2(f1, f1);
            const ulonglong2* xr = (const ulonglong2*)(sbuf + (c8 + k) * 32);
#pragma unroll
            for (int j = 0; j < 8; j++) {
                ulonglong2 x2 = xr[j];
                fma2(acc0[2 * j],     w2a, x2.x); fma2(acc0[2 * j + 1], w2a, x2.y);
                fma2(acc1[2 * j],     w2b, x2.x); fma2(acc1[2 * j + 1], w2b, x2.y);
            }
        }
    }
    __syncthreads();
#pragma unroll
    for (int j = 0; j < 16; j++) {
        float lo, hi;
        upk2(lo, hi, acc0[j]);
        sbuf[oc0 * 33 + 2 * j]     = gelu_f(lo);
        sbuf[oc0 * 33 + 2 * j + 1] = gelu_f(hi);
        upk2(lo, hi, acc1[j]);
        sbuf[(oc0 + 1) * 33 + 2 * j]     = gelu_f(lo);
        sbuf[(oc0 + 1) * 33 + 2 * j + 1] = gelu_f(hi);
    }
    __syncthreads();
    float* ob = g_m1 + ((long)b * 256) * 65536 + pp0;
#pragma unroll 4
    for (int i = t; i < 8192; i += 128) {
        int o = i >> 5, p = i & 31;
        ob[(long)o * 65536 + p] = sbuf[o * 33 + p];
    }
}

// ==================================================================
// K8: m2 = gelu(depthwise 3x3, 256 ch), 8 rows per block
// ==================================================================
__global__ void __launch_bounds__(256) k_m2(
    const float* __restrict__ w, const float* __restrict__ bias)
{
    int r0 = blockIdx.x * 8;
    int bc = blockIdx.y;
    int c = bc & 255;
    const float* base = g_m1 + (long)bc * 65536;
    __shared__ float srow[10][258];
    for (int i = threadIdx.x; i < 10 * 258; i += 256) {
        int row = i / 258, xx = i % 258;
        int yy = r0 - 1 + row, x = xx - 1;
        srow[row][xx] = (yy >= 0 && yy < 256 && x >= 0 && x < 256) ? base[yy * 256 + x] : 0.f;
    }
    __syncthreads();
    float wl[9];
#pragma unroll
    for (int i = 0; i < 9; i++) wl[i] = w[c * 9 + i];
    float bv = bias[c];
    int x = threadIdx.x;
#pragma unroll
    for (int rr = 0; rr < 8; rr++) {
        float acc = bv;
#pragma unroll
        for (int ky = 0; ky < 3; ky++)
#pragma unroll
            for (int kx = 0; kx < 3; kx++)
                acc += srow[rr + ky][x + kx] * wl[ky * 3 + kx];
        g_m2[(long)bc * 65536 + (long)(r0 + rr) * 256 + x] = gelu_f(acc);
    }
}

// ==================================================================
// K9: out += conv1x1(m2, 256->128)
// ==================================================================
__global__ void __launch_bounds__(64) k_m3(
    float* __restrict__ out, const float* __restrict__ bias)
{
    __shared__ __align__(16) float sbuf[8448];
    __shared__ __align__(16) float s_wT[1024];
    int t = threadIdx.x;
    long pix0 = (long)blockIdx.x * 32;
    int b = (int)(pix0 >> 16);
    int pp0 = (int)(pix0 & 65535);
    const float* ib = g_m2 + ((long)b * 256) * 65536 + pp0;
#pragma unroll 8
    for (int i = t; i < 8192; i += 64) {
        int ic = i >> 5, p = i & 31;
        sbuf[i] = ib[(long)ic * 65536 + p];
    }
    int oc0 = 2 * t;
    float b0 = bias[oc0], b1 = bias[oc0 + 1];
    ull acc0[16], acc1[16];
#pragma unroll
    for (int j = 0; j < 16; j++) { acc0[j] = pk2(b0, b0); acc1[j] = pk2(b1, b1); }

    for (int c8 = 0; c8 < 256; c8 += 8) {
        __syncthreads();
        for (int i = t; i < 256; i += 64)
            *(float4*)(s_wT + i * 4) = *(const float4*)(g_w3T + c8 * 128 + i * 4);
        __syncthreads();
#pragma unroll
        for (int k = 0; k < 8; k++) {
            ull wp = *(const ull*)(s_wT + k * 128 + oc0);
            float f0, f1; upk2(f0, f1, wp);
            ull w2a = pk2(f0, f0), w2b = pk2(f1, f1);
            const ulonglong2* xr = (const ulonglong2*)(sbuf + (c8 + k) * 32);
#pragma unroll
            for (int j = 0; j < 8; j++) {
                ulonglong2 x2 = xr[j];
                fma2(acc0[2 * j],     w2a, x2.x); fma2(acc0[2 * j + 1], w2a, x2.y);
                fma2(acc1[2 * j],     w2b, x2.x); fma2(acc1[2 * j + 1], w2b, x2.y);
            }
        }
    }
    __syncthreads();
#pragma unroll
    for (int j = 0; j < 16; j++) {
        float lo, hi;
        upk2(lo, hi, acc0[j]);
        sbuf[oc0 * 33 + 2 * j]     = lo;
        sbuf[oc0 * 33 + 2 * j + 1] = hi;
        upk2(lo, hi, acc1[j]);
        sbuf[(oc0 + 1) * 33 + 2 * j]     = lo;
        sbuf[(oc0 + 1) * 33 + 2 * j + 1] = hi;
    }
    __syncthreads();
    float* ob = out + ((long)b * 128) * 65536 + pp0;
#pragma unroll 8
    for (int i = t; i < 4096; i += 64) {
        int o = i >> 5, p = i & 31;
        long a = (long)o * 65536 + p;
        ob[a] = ob[a] + sbuf[o * 33 + p];
    }
}

// ==================================================================
extern "C" void kernel_launch(void* const* d_in, const int* in_sizes, int n_in,
                              void* d_out, int out_size)
{
    const float* x1  = (const float*)d_in[0];
    const float* x2  = (const float*)d_in[1];
    const float* q1w = (const float*)d_in[2];  const float* q1b = (const float*)d_in[3];
    const float* q2w = (const float*)d_in[4];  const float* q2b = (const float*)d_in[5];
    const float* k1w = (const float*)d_in[6];  const float* k1b = (const float*)d_in[7];
    const float* k2w = (const float*)d_in[8];  const float* k2b = (const float*)d_in[9];
    const float* v1w = (const float*)d_in[10]; const float* v1b = (const float*)d_in[11];
    const float* v2w = (const float*)d_in[12]; const float* v2b = (const float*)d_in[13];
    const float* rw  = (const float*)d_in[14]; const float* rb  = (const float*)d_in[15];
    const float* m1w = (const float*)d_in[16]; const float* m1b = (const float*)d_in[17];
    const float* m2w = (const float*)d_in[18]; const float* m2b = (const float*)d_in[19];
    const float* m3w = (const float*)d_in[20]; const float* m3b = (const float*)d_in[21];
    float* out = (float*)d_out;

    void* tq_addr = nullptr;
    cudaGetSymbolAddress(&tq_addr, g_tq);

    k_prep<<<800, 256>>>(m1w, m3w, rw, q1w, k1w, v1w);                     // idx 0
    k_qkv1x1<<<4096, 256>>>(x1, x2, q1b, k1b, v1b);                        // idx 1
    k_dw_squeeze<<<dim3(32, 256, 3), 128>>>(q2w, q2b, k2w, k2b, v2w, v2b); // idx 2
    // small profiling probe (ncu captures idx 3): 256-block conv v3, dead g_tq
    k_conv5x5<<<dim3(1, 32, 8), 256>>>(rb, (float*)tq_addr);               // idx 3
    k_ksoftmax<<<256, 256>>>();                                            // idx 4
    k_zero_ctx<<<16, 256>>>();                                             // idx 5
    k_ctx<<<dim3(16, 128), 256>>>();                                       // idx 6
    k_att<<<dim3(256, 4), 128>>>();                                        // idx 7
    k_conv5x5<<<dim3(4, 32, 32), 256>>>(rb, out);                          // idx 8
    k_m1<<<8192, 128>>>(out, m1b);                                         // idx 9
    k_m2<<<dim3(32, 1024), 256>>>(m2w, m2b);                               // idx 10
    k_m3<<<8192, 64>>>(out, m3b);                                          // idx 11
}